// round 6
// baseline (speedup 1.0000x reference)
#include <cuda_runtime.h>

#define BATCH 4096
#define HDIM  128
#define G3    384
#define NL    4
#define TENC  64
#define TTGT  100
#define TSTEPS 163
#define BC    16
#define NCTA  256
#define NTHR  128

// output layout: concatenated flattened outputs, fp32
// (decoder_output, dec_hidden, encoder_output, enc_hidden, loss)
static constexpr size_t OFF_DECOUT = 0;
static constexpr size_t OFF_DECH   = (size_t)BATCH * TTGT * 4;                    // 1,638,400
static constexpr size_t OFF_ENCOUT = OFF_DECH + (size_t)NL * BATCH * HDIM;        // 3,735,552
static constexpr size_t OFF_ENCH   = OFF_ENCOUT + (size_t)BATCH * TENC * HDIM;    // 37,289,984
static constexpr size_t OFF_LOSS   = OFF_ENCH + (size_t)NL * BATCH * HDIM;        // 39,387,136

__device__ float g_lossPart[NCTA];

// single dynamic smem region (floats), total 12288 floats = 49152 B = 48 KB exactly
//   [0, 8192)      h[4][16][128]
//   [8192, 8704)   br[4][128]  = bih_r + bhh_r
//   [8704, 9216)   bz[4][128]  = bih_z + bhh_z
//   [9216, 9728)   bin[4][128] = bih_n
//   [9728,10240)   bhn[4][128] = bhh_n
//   [10240,12288)  o1[16][128]  (decoder lin1 staging; reused as reduction scratch at end)
#define SM_H    0
#define SM_BR   8192
#define SM_BZ   8704
#define SM_BIN  9216
#define SM_BHN  9728
#define SM_O1   10240
#define SM_RED  10240
#define SM_FLOATS 12288

__device__ __forceinline__ float sigm(float x)  { return 1.0f / (1.0f + __expf(-x)); }
__device__ __forceinline__ float tanha(float x) { return 1.0f - 2.0f / (1.0f + __expf(2.0f * x)); }

__device__ __forceinline__ float dot4(float4 a, float4 b) {
    return a.x * b.x + a.y * b.y + a.z * b.z + a.w * b.w;
}

// accumulate 3 gate GEMMs: aA += v * W[rows j],  aB += v * W[rows j+128],  aC += v * W[rows j+256]
__device__ __forceinline__ void accum_pair3(
    float (&aA)[4][4], float (&aB)[4][4], float (&aC)[4][4],
    const float* __restrict__ W, const float* __restrict__ vbase,
    int b0, int j0)
{
#pragma unroll 2
    for (int k0 = 0; k0 < HDIM; k0 += 4) {
        float4 v[4];
#pragma unroll
        for (int bb = 0; bb < 4; ++bb)
            v[bb] = *(const float4*)(vbase + (b0 + bb) * HDIM + k0);
#pragma unroll
        for (int jj = 0; jj < 4; ++jj) {
            int r = j0 + jj;
            float4 w0 = __ldg((const float4*)(W + r * HDIM + k0));
            float4 w1 = __ldg((const float4*)(W + (r + HDIM) * HDIM + k0));
            float4 w2 = __ldg((const float4*)(W + (r + 2 * HDIM) * HDIM + k0));
#pragma unroll
            for (int bb = 0; bb < 4; ++bb) {
                aA[bb][jj] += dot4(v[bb], w0);
                aB[bb][jj] += dot4(v[bb], w1);
                aC[bb][jj] += dot4(v[bb], w2);
            }
        }
    }
}

// single GEMM (lin1)
__device__ __forceinline__ void accum_one(
    float (&aA)[4][4],
    const float* __restrict__ W, const float* __restrict__ vbase,
    int b0, int j0)
{
#pragma unroll 2
    for (int k0 = 0; k0 < HDIM; k0 += 4) {
        float4 v[4];
#pragma unroll
        for (int bb = 0; bb < 4; ++bb)
            v[bb] = *(const float4*)(vbase + (b0 + bb) * HDIM + k0);
#pragma unroll
        for (int jj = 0; jj < 4; ++jj) {
            float4 w = __ldg((const float4*)(W + (j0 + jj) * HDIM + k0));
#pragma unroll
            for (int bb = 0; bb < 4; ++bb)
                aA[bb][jj] += dot4(v[bb], w);
        }
    }
}

__device__ __forceinline__ void load_biases(float* SH,
                                            const float* __restrict__ bih,
                                            const float* __restrict__ bhh,
                                            int tid)
{
    for (int i = tid; i < NL * HDIM; i += NTHR) {
        int l = i >> 7;
        int j = i & 127;
        SH[SM_BR  + i] = bih[l * G3 + j]            + bhh[l * G3 + j];
        SH[SM_BZ  + i] = bih[l * G3 + HDIM + j]     + bhh[l * G3 + HDIM + j];
        SH[SM_BIN + i] = bih[l * G3 + 2 * HDIM + j];
        SH[SM_BHN + i] = bhh[l * G3 + 2 * HDIM + j];
    }
}

__global__ void __launch_bounds__(NTHR)
gru_seq2seq_kernel(
    const float* __restrict__ inp,      // (4096, 64, 4)
    const float* __restrict__ tgt,      // (4096, 100, 4)
    const float* __restrict__ e_wih0,   // (384, 4)
    const float* __restrict__ e_whh0,   // (384, 128)
    const float* __restrict__ e_wih,    // (3, 384, 128)
    const float* __restrict__ e_whh,    // (3, 384, 128)
    const float* __restrict__ e_bih,    // (4, 384)
    const float* __restrict__ e_bhh,    // (4, 384)
    const float* __restrict__ d_wih0,
    const float* __restrict__ d_whh0,
    const float* __restrict__ d_wih,
    const float* __restrict__ d_whh,
    const float* __restrict__ d_bih,
    const float* __restrict__ d_bhh,
    const float* __restrict__ l1w,      // (128, 128)
    const float* __restrict__ l1b,      // (128)
    const float* __restrict__ l2w,      // (4, 128)
    const float* __restrict__ l2b,      // (4)
    float* __restrict__ out)
{
    extern __shared__ __align__(16) float SH[];

    const int tid = threadIdx.x;
    const int cta = blockIdx.x;
    const int bt  = tid & 3;
    const int jt  = tid >> 2;
    const int b0  = bt * 4;            // local batch-row base (covers b0..b0+3)
    const int j0  = jt * 4;            // hidden-unit base (covers j0..j0+3)
    const size_t bg0 = (size_t)cta * BC;

    // init: zero hidden, load encoder biases
    for (int i = tid; i < NL * BC * HDIM; i += NTHR) SH[SM_H + i] = 0.0f;
    load_biases(SH, e_bih, e_bhh, tid);
    __syncthreads();

    float lossAcc = 0.0f;

    for (int t = 0; t < TSTEPS; ++t) {
        const bool enc = (t < TENC);

        if (t == TENC) {
            // snapshot enc_hidden (L, B, H)
            for (int i = tid; i < NL * BC * HDIM; i += NTHR) {
                int l = i >> 11;
                int b = (i >> 7) & 15;
                int j = i & 127;
                out[OFF_ENCH + (size_t)l * BATCH * HDIM + (bg0 + b) * HDIM + j] = SH[SM_H + i];
            }
            // switch biases to decoder
            load_biases(SH, d_bih, d_bhh, tid);
            // decoder_output[:, 0, :] = inp[:, 0, :]
            if (tid < BC * 4) {
                int b = tid >> 2, e = tid & 3;
                out[OFF_DECOUT + (bg0 + b) * (TTGT * 4) + e] = inp[(bg0 + b) * (TENC * 4) + e];
            }
            __syncthreads();
        }

        const float* wih0 = enc ? e_wih0 : d_wih0;
        const float* whh0 = enc ? e_whh0 : d_whh0;
        const float* wihL = enc ? e_wih  : d_wih;
        const float* whhL = enc ? e_whh  : d_whh;

        for (int l = 0; l < NL; ++l) {
            float aR[4][4], aZ[4][4], aIN[4][4], aHN[4][4];
#pragma unroll
            for (int jj = 0; jj < 4; ++jj) {
                float br = SH[SM_BR  + l * HDIM + j0 + jj];
                float bz = SH[SM_BZ  + l * HDIM + j0 + jj];
                float bi = SH[SM_BIN + l * HDIM + j0 + jj];
                float bh = SH[SM_BHN + l * HDIM + j0 + jj];
#pragma unroll
                for (int bb = 0; bb < 4; ++bb) {
                    aR[bb][jj] = br; aZ[bb][jj] = bz; aIN[bb][jj] = bi; aHN[bb][jj] = bh;
                }
            }

            if (l == 0) {
                // input GEMM with E=4 input
                const float* xrow;
                int xstr;
                if (enc)              { xrow = inp + (size_t)t * 4;            xstr = TENC * 4; }
                else if (t == TENC)   { xrow = inp;                            xstr = TENC * 4; }
                else                  { xrow = tgt + (size_t)(t - TENC) * 4;   xstr = TTGT * 4; }

                float4 xv[4];
#pragma unroll
                for (int bb = 0; bb < 4; ++bb)
                    xv[bb] = __ldg((const float4*)(xrow + (bg0 + b0 + bb) * xstr));
#pragma unroll
                for (int jj = 0; jj < 4; ++jj) {
                    int r = j0 + jj;
                    float4 w0 = __ldg((const float4*)(wih0 + r * 4));
                    float4 w1 = __ldg((const float4*)(wih0 + (r + HDIM) * 4));
                    float4 w2 = __ldg((const float4*)(wih0 + (r + 2 * HDIM) * 4));
#pragma unroll
                    for (int bb = 0; bb < 4; ++bb) {
                        aR[bb][jj]  += dot4(xv[bb], w0);
                        aZ[bb][jj]  += dot4(xv[bb], w1);
                        aIN[bb][jj] += dot4(xv[bb], w2);
                    }
                }
                accum_pair3(aR, aZ, aHN, whh0, SH + SM_H + 0 * BC * HDIM, b0, j0);
            } else {
                const float* wih = wihL + (size_t)(l - 1) * G3 * HDIM;
                const float* whh = whhL + (size_t)(l - 1) * G3 * HDIM;
                accum_pair3(aR, aZ, aIN, wih, SH + SM_H + (l - 1) * BC * HDIM, b0, j0); // x = h[l-1] (new)
                accum_pair3(aR, aZ, aHN, whh, SH + SM_H + l * BC * HDIM, b0, j0);       // h = h[l] (old)
            }

            __syncthreads();   // all reads of h[l] done before overwrite

            // gate phase
            {
                float* hl = SH + SM_H + l * BC * HDIM;
                const bool wrEnc = (l == NL - 1) && enc;
#pragma unroll
                for (int bb = 0; bb < 4; ++bb) {
                    float4 hnew4;
                    float* hrow = hl + (b0 + bb) * HDIM + j0;
#pragma unroll
                    for (int jj = 0; jj < 4; ++jj) {
                        float r  = sigm(aR[bb][jj]);
                        float z  = sigm(aZ[bb][jj]);
                        float n  = tanha(aIN[bb][jj] + r * aHN[bb][jj]);
                        float ho = hrow[jj];
                        float hv = n + z * (ho - n);
                        hrow[jj] = hv;
                        (&hnew4.x)[jj] = hv;
                    }
                    if (wrEnc) {
                        *(float4*)(out + OFF_ENCOUT +
                                   (bg0 + b0 + bb) * (size_t)(TENC * HDIM) +
                                   (size_t)t * HDIM + j0) = hnew4;
                    }
                }
            }
            __syncthreads();   // h[l] new values visible before next layer reads
        }

        if (!enc) {
            const int td = t - TENC;
            // lin1 + relu into o1 staging
            float a1[4][4];
#pragma unroll
            for (int jj = 0; jj < 4; ++jj) {
                float b1 = __ldg(l1b + j0 + jj);
#pragma unroll
                for (int bb = 0; bb < 4; ++bb) a1[bb][jj] = b1;
            }
            accum_one(a1, l1w, SH + SM_H + (NL - 1) * BC * HDIM, b0, j0);
#pragma unroll
            for (int bb = 0; bb < 4; ++bb)
#pragma unroll
                for (int jj = 0; jj < 4; ++jj)
                    SH[SM_O1 + (b0 + bb) * HDIM + j0 + jj] = fmaxf(a1[bb][jj], 0.0f);
            __syncthreads();

            // lin2 + output + loss (64 threads, one (b,e) each)
            if (tid < BC * 4) {
                int b = tid >> 2, e = tid & 3;
                float acc = __ldg(l2b + e);
                const float* orow = SH + SM_O1 + b * HDIM;
                const float* wrow = l2w + e * HDIM;
#pragma unroll 8
                for (int k0 = 0; k0 < HDIM; k0 += 4) {
                    float4 a4 = *(const float4*)(orow + k0);
                    float4 w4 = __ldg((const float4*)(wrow + k0));
                    acc += dot4(a4, w4);
                }
                size_t gb = bg0 + b;
                out[OFF_DECOUT + gb * (TTGT * 4) + (size_t)(td + 1) * 4 + e] = acc;
                float y = __ldg(tgt + gb * (TTGT * 4) + (size_t)(td + 1) * 4 + e);
                float d = acc - y;
                lossAcc += d * d;
            }
            // no sync needed: next write to o1 is behind next step's barriers
        }
    }

    __syncthreads();
    // dec_hidden (final h) -> out
    for (int i = tid; i < NL * BC * HDIM; i += NTHR) {
        int l = i >> 11;
        int b = (i >> 7) & 15;
        int j = i & 127;
        out[OFF_DECH + (size_t)l * BATCH * HDIM + (bg0 + b) * HDIM + j] = SH[SM_H + i];
    }

    // deterministic CTA loss partial (reuse o1 region as scratch; o1 dead now)
    __syncthreads();
    SH[SM_RED + tid] = lossAcc;
    __syncthreads();
    for (int o = NTHR / 2; o > 0; o >>= 1) {
        if (tid < o) SH[SM_RED + tid] += SH[SM_RED + tid + o];
        __syncthreads();
    }
    if (tid == 0) g_lossPart[cta] = SH[SM_RED];
}

__global__ void loss_reduce_kernel(float* __restrict__ out)
{
    __shared__ float s[NCTA];
    int tid = threadIdx.x;
    s[tid] = g_lossPart[tid];
    __syncthreads();
    for (int o = NCTA / 2; o > 0; o >>= 1) {
        if (tid < o) s[tid] += s[tid + o];
        __syncthreads();
    }
    if (tid == 0) out[OFF_LOSS] = s[0] * (1.0f / (float)(BATCH * 4));
}

extern "C" void kernel_launch(void* const* d_in, const int* in_sizes, int n_in,
                              void* d_out, int out_size)
{
    const float* inp    = (const float*)d_in[0];
    const float* tgt    = (const float*)d_in[1];
    const float* e_wih0 = (const float*)d_in[2];
    const float* e_whh0 = (const float*)d_in[3];
    const float* e_wih  = (const float*)d_in[4];
    const float* e_whh  = (const float*)d_in[5];
    const float* e_bih  = (const float*)d_in[6];
    const float* e_bhh  = (const float*)d_in[7];
    const float* d_wih0 = (const float*)d_in[8];
    const float* d_whh0 = (const float*)d_in[9];
    const float* d_wih  = (const float*)d_in[10];
    const float* d_whh  = (const float*)d_in[11];
    const float* d_bih  = (const float*)d_in[12];
    const float* d_bhh  = (const float*)d_in[13];
    const float* l1w    = (const float*)d_in[14];
    const float* l1b    = (const float*)d_in[15];
    const float* l2w    = (const float*)d_in[16];
    const float* l2b    = (const float*)d_in[17];
    float* out = (float*)d_out;

    gru_seq2seq_kernel<<<NCTA, NTHR, SM_FLOATS * sizeof(float)>>>(
        inp, tgt, e_wih0, e_whh0, e_wih, e_whh, e_bih, e_bhh,
        d_wih0, d_whh0, d_wih, d_whh, d_bih, d_bhh,
        l1w, l1b, l2w, l2b, out);
    loss_reduce_kernel<<<1, NCTA>>>(out);
}

// round 7
// speedup vs baseline: 1.5640x; 1.5640x over previous
#include <cuda_runtime.h>

#define BATCH 4096
#define HDIM  128
#define G3    384
#define NL    4
#define TENC  64
#define TTGT  100
#define TSTEPS 163
#define BC    16
#define NCTA  256
#define NTHR  256

typedef unsigned long long u64;

// output layout: concatenated flattened outputs, fp32
// (decoder_output, dec_hidden, encoder_output, enc_hidden, loss)
static constexpr size_t OFF_DECOUT = 0;
static constexpr size_t OFF_DECH   = (size_t)BATCH * TTGT * 4;                    // 1,638,400
static constexpr size_t OFF_ENCOUT = OFF_DECH + (size_t)NL * BATCH * HDIM;        // 3,735,552
static constexpr size_t OFF_ENCH   = OFF_ENCOUT + (size_t)BATCH * TENC * HDIM;    // 37,289,984
static constexpr size_t OFF_LOSS   = OFF_ENCH + (size_t)NL * BATCH * HDIM;        // 39,387,136

__device__ float g_lossPart[NCTA];

// single dynamic smem region (floats), total 12288 floats = 49152 B = 48 KB exactly
//   [0, 8192)      h[4][16][128]   (16B-chunk XOR-swizzled per row, see swz())
//   [8192, 8704)   br[4][128]  = bih_r + bhh_r
//   [8704, 9216)   bz[4][128]  = bih_z + bhh_z
//   [9216, 9728)   bin[4][128] = bih_n
//   [9728,10240)   bhn[4][128] = bhh_n
//   [10240,12288)  o1[16][128]  (decoder lin1 staging; reused as reduction scratch at end)
#define SM_H    0
#define SM_BR   8192
#define SM_BZ   8704
#define SM_BIN  9216
#define SM_BHN  9728
#define SM_O1   10240
#define SM_RED  10240
#define SM_FLOATS 12288

// swizzle: 16B chunk index c within a 128-float row m maps to c ^ (m>>1).
// The 8 distinct rows touched by one warp-wide v-load (rows = bt*2+bb, bt=0..7,
// fixed bb) get 8 distinct bank-quartet starts -> conflict-free LDS.128.
__device__ __forceinline__ int swz(int row, int k0) {   // k0 multiple of 4
    return (((k0 >> 2) ^ (row >> 1)) & 31) << 2;
}
__device__ __forceinline__ int swz_j(int row, int j) {  // scalar j
    return (((((j >> 2) ^ (row >> 1)) & 31) << 2) | (j & 3));
}

__device__ __forceinline__ float sigm(float x)  { return 1.0f / (1.0f + __expf(-x)); }
__device__ __forceinline__ float tanha(float x) { return 1.0f - 2.0f / (1.0f + __expf(2.0f * x)); }

__device__ __forceinline__ void pfma(u64& d, u64 a, u64 b) {
    asm("fma.rn.f32x2 %0, %1, %2, %0;" : "+l"(d) : "l"(a), "l"(b));
}
__device__ __forceinline__ float hsum2(u64 v) {
    float lo, hi;
    asm("mov.b64 {%0, %1}, %2;" : "=f"(lo), "=f"(hi) : "l"(v));
    return lo + hi;
}

// packed 3-gate GEMM: p{A,B,C}[bb][jj] += h[b0+bb][k] * W[(j0+jj)+{0,128,256}][k]
__device__ __forceinline__ void accum3_p(
    u64 (&aA)[2][4], u64 (&aB)[2][4], u64 (&aC)[2][4],
    const float* __restrict__ W, const float* __restrict__ hbase,
    int b0, int j0)
{
#pragma unroll 2
    for (int k0 = 0; k0 < HDIM; k0 += 4) {
        longlong2 v0 = *(const longlong2*)(hbase + (b0    ) * HDIM + swz(b0,     k0));
        longlong2 v1 = *(const longlong2*)(hbase + (b0 + 1) * HDIM + swz(b0 + 1, k0));
#pragma unroll
        for (int jj = 0; jj < 4; ++jj) {
            int r = j0 + jj;
            longlong2 w0 = __ldg((const longlong2*)(W + (size_t)r * HDIM + k0));
            longlong2 w1 = __ldg((const longlong2*)(W + (size_t)(r +     HDIM) * HDIM + k0));
            longlong2 w2 = __ldg((const longlong2*)(W + (size_t)(r + 2 * HDIM) * HDIM + k0));
            pfma(aA[0][jj], (u64)v0.x, (u64)w0.x); pfma(aA[0][jj], (u64)v0.y, (u64)w0.y);
            pfma(aA[1][jj], (u64)v1.x, (u64)w0.x); pfma(aA[1][jj], (u64)v1.y, (u64)w0.y);
            pfma(aB[0][jj], (u64)v0.x, (u64)w1.x); pfma(aB[0][jj], (u64)v0.y, (u64)w1.y);
            pfma(aB[1][jj], (u64)v1.x, (u64)w1.x); pfma(aB[1][jj], (u64)v1.y, (u64)w1.y);
            pfma(aC[0][jj], (u64)v0.x, (u64)w2.x); pfma(aC[0][jj], (u64)v0.y, (u64)w2.y);
            pfma(aC[1][jj], (u64)v1.x, (u64)w2.x); pfma(aC[1][jj], (u64)v1.y, (u64)w2.y);
        }
    }
}

// packed single GEMM (lin1)
__device__ __forceinline__ void accum1_p(
    u64 (&aA)[2][4],
    const float* __restrict__ W, const float* __restrict__ hbase,
    int b0, int j0)
{
#pragma unroll 2
    for (int k0 = 0; k0 < HDIM; k0 += 4) {
        longlong2 v0 = *(const longlong2*)(hbase + (b0    ) * HDIM + swz(b0,     k0));
        longlong2 v1 = *(const longlong2*)(hbase + (b0 + 1) * HDIM + swz(b0 + 1, k0));
#pragma unroll
        for (int jj = 0; jj < 4; ++jj) {
            longlong2 w = __ldg((const longlong2*)(W + (size_t)(j0 + jj) * HDIM + k0));
            pfma(aA[0][jj], (u64)v0.x, (u64)w.x); pfma(aA[0][jj], (u64)v0.y, (u64)w.y);
            pfma(aA[1][jj], (u64)v1.x, (u64)w.x); pfma(aA[1][jj], (u64)v1.y, (u64)w.y);
        }
    }
}

__device__ __forceinline__ void load_biases(float* SH,
                                            const float* __restrict__ bih,
                                            const float* __restrict__ bhh,
                                            int tid)
{
    for (int i = tid; i < NL * HDIM; i += NTHR) {
        int l = i >> 7;
        int j = i & 127;
        SH[SM_BR  + i] = bih[l * G3 + j]            + bhh[l * G3 + j];
        SH[SM_BZ  + i] = bih[l * G3 + HDIM + j]     + bhh[l * G3 + HDIM + j];
        SH[SM_BIN + i] = bih[l * G3 + 2 * HDIM + j];
        SH[SM_BHN + i] = bhh[l * G3 + 2 * HDIM + j];
    }
}

__global__ void __launch_bounds__(NTHR, 2)
gru_seq2seq_kernel(
    const float* __restrict__ inp,      // (4096, 64, 4)
    const float* __restrict__ tgt,      // (4096, 100, 4)
    const float* __restrict__ e_wih0,   // (384, 4)
    const float* __restrict__ e_whh0,   // (384, 128)
    const float* __restrict__ e_wih,    // (3, 384, 128)
    const float* __restrict__ e_whh,    // (3, 384, 128)
    const float* __restrict__ e_bih,    // (4, 384)
    const float* __restrict__ e_bhh,    // (4, 384)
    const float* __restrict__ d_wih0,
    const float* __restrict__ d_whh0,
    const float* __restrict__ d_wih,
    const float* __restrict__ d_whh,
    const float* __restrict__ d_bih,
    const float* __restrict__ d_bhh,
    const float* __restrict__ l1w,      // (128, 128)
    const float* __restrict__ l1b,      // (128)
    const float* __restrict__ l2w,      // (4, 128)
    const float* __restrict__ l2b,      // (4)
    float* __restrict__ out)
{
    extern __shared__ __align__(16) float SH[];

    const int tid = threadIdx.x;
    const int cta = blockIdx.x;
    const int bt  = tid & 7;
    const int jt  = tid >> 3;
    const int b0  = bt * 2;            // local batch-row base (covers b0, b0+1)
    const int j0  = jt * 4;            // hidden-unit base (covers j0..j0+3)
    const size_t bg0 = (size_t)cta * BC;

    // init: zero hidden, load encoder biases
    for (int i = tid; i < NL * BC * HDIM; i += NTHR) SH[SM_H + i] = 0.0f;
    load_biases(SH, e_bih, e_bhh, tid);
    __syncthreads();

    float lossAcc = 0.0f;

    for (int t = 0; t < TSTEPS; ++t) {
        const bool enc = (t < TENC);

        if (t == TENC) {
            // snapshot enc_hidden (L, B, H) — de-swizzle
            for (int i = tid; i < NL * BC * HDIM; i += NTHR) {
                int l = i >> 11;
                int b = (i >> 7) & 15;
                int j = i & 127;
                out[OFF_ENCH + (size_t)l * BATCH * HDIM + (bg0 + b) * HDIM + j] =
                    SH[SM_H + l * BC * HDIM + b * HDIM + swz_j(b, j)];
            }
            // switch biases to decoder
            load_biases(SH, d_bih, d_bhh, tid);
            // decoder_output[:, 0, :] = inp[:, 0, :]
            if (tid < BC * 4) {
                int b = tid >> 2, e = tid & 3;
                out[OFF_DECOUT + (bg0 + b) * (TTGT * 4) + e] = inp[(bg0 + b) * (TENC * 4) + e];
            }
            __syncthreads();
        }

        const float* wih0 = enc ? e_wih0 : d_wih0;
        const float* whh0 = enc ? e_whh0 : d_whh0;
        const float* wihL = enc ? e_wih  : d_wih;
        const float* whhL = enc ? e_whh  : d_whh;

        for (int l = 0; l < NL; ++l) {
            u64 pR[2][4]  = {};
            u64 pZ[2][4]  = {};
            u64 pIN[2][4] = {};
            u64 pHN[2][4] = {};

            if (l == 0) {
                // packed input GEMM with E=4 input (2 pfma per gate per bb)
                const float* xrow;
                int xstr;
                if (enc)              { xrow = inp + (size_t)t * 4;            xstr = TENC * 4; }
                else if (t == TENC)   { xrow = inp;                            xstr = TENC * 4; }
                else                  { xrow = tgt + (size_t)(t - TENC) * 4;   xstr = TTGT * 4; }

                longlong2 xv0 = __ldg((const longlong2*)(xrow + (bg0 + b0)     * xstr));
                longlong2 xv1 = __ldg((const longlong2*)(xrow + (bg0 + b0 + 1) * xstr));
#pragma unroll
                for (int jj = 0; jj < 4; ++jj) {
                    int r = j0 + jj;
                    longlong2 w0 = __ldg((const longlong2*)(wih0 + r * 4));
                    longlong2 w1 = __ldg((const longlong2*)(wih0 + (r +     HDIM) * 4));
                    longlong2 w2 = __ldg((const longlong2*)(wih0 + (r + 2 * HDIM) * 4));
                    pfma(pR[0][jj],  (u64)xv0.x, (u64)w0.x); pfma(pR[0][jj],  (u64)xv0.y, (u64)w0.y);
                    pfma(pR[1][jj],  (u64)xv1.x, (u64)w0.x); pfma(pR[1][jj],  (u64)xv1.y, (u64)w0.y);
                    pfma(pZ[0][jj],  (u64)xv0.x, (u64)w1.x); pfma(pZ[0][jj],  (u64)xv0.y, (u64)w1.y);
                    pfma(pZ[1][jj],  (u64)xv1.x, (u64)w1.x); pfma(pZ[1][jj],  (u64)xv1.y, (u64)w1.y);
                    pfma(pIN[0][jj], (u64)xv0.x, (u64)w2.x); pfma(pIN[0][jj], (u64)xv0.y, (u64)w2.y);
                    pfma(pIN[1][jj], (u64)xv1.x, (u64)w2.x); pfma(pIN[1][jj], (u64)xv1.y, (u64)w2.y);
                }
                accum3_p(pR, pZ, pHN, whh0, SH + SM_H + 0 * BC * HDIM, b0, j0);
            } else {
                const float* wih = wihL + (size_t)(l - 1) * G3 * HDIM;
                const float* whh = whhL + (size_t)(l - 1) * G3 * HDIM;
                accum3_p(pR, pZ, pIN, wih, SH + SM_H + (l - 1) * BC * HDIM, b0, j0); // x = h[l-1] (new)
                accum3_p(pR, pZ, pHN, whh, SH + SM_H + l * BC * HDIM, b0, j0);       // h = h[l] (old)
            }

            __syncthreads();   // all reads of h[l] done before overwrite

            // gate phase
            {
                float* hl = SH + SM_H + l * BC * HDIM;
                const bool wrEnc = (l == NL - 1) && enc;
                float bR4[4], bZ4[4], bI4[4], bH4[4];
#pragma unroll
                for (int jj = 0; jj < 4; ++jj) {
                    bR4[jj] = SH[SM_BR  + l * HDIM + j0 + jj];
                    bZ4[jj] = SH[SM_BZ  + l * HDIM + j0 + jj];
                    bI4[jj] = SH[SM_BIN + l * HDIM + j0 + jj];
                    bH4[jj] = SH[SM_BHN + l * HDIM + j0 + jj];
                }
#pragma unroll
                for (int bb = 0; bb < 2; ++bb) {
                    int row = b0 + bb;
                    float* hrow = hl + row * HDIM + swz(row, j0);
                    float4 hold = *(const float4*)hrow;
                    float4 hnew;
#pragma unroll
                    for (int jj = 0; jj < 4; ++jj) {
                        float r = sigm(bR4[jj] + hsum2(pR[bb][jj]));
                        float z = sigm(bZ4[jj] + hsum2(pZ[bb][jj]));
                        float n = tanha(bI4[jj] + hsum2(pIN[bb][jj]) +
                                        r * (bH4[jj] + hsum2(pHN[bb][jj])));
                        float ho = (&hold.x)[jj];
                        (&hnew.x)[jj] = n + z * (ho - n);
                    }
                    *(float4*)hrow = hnew;
                    if (wrEnc) {
                        *(float4*)(out + OFF_ENCOUT +
                                   (bg0 + row) * (size_t)(TENC * HDIM) +
                                   (size_t)t * HDIM + j0) = hnew;
                    }
                }
            }
            __syncthreads();   // h[l] new values visible before next layer reads
        }

        if (!enc) {
            const int td = t - TENC;
            // lin1 + relu into o1 staging (o1 unswizzled)
            u64 p1[2][4] = {};
            accum1_p(p1, l1w, SH + SM_H + (NL - 1) * BC * HDIM, b0, j0);
#pragma unroll
            for (int bb = 0; bb < 2; ++bb)
#pragma unroll
                for (int jj = 0; jj < 4; ++jj) {
                    float v = __ldg(l1b + j0 + jj) + hsum2(p1[bb][jj]);
                    SH[SM_O1 + (b0 + bb) * HDIM + j0 + jj] = fmaxf(v, 0.0f);
                }
            __syncthreads();

            // lin2 + output + loss (64 threads, one (b,e) each)
            if (tid < BC * 4) {
                int b = tid >> 2, e = tid & 3;
                float acc = __ldg(l2b + e);
                const float* orow = SH + SM_O1 + b * HDIM;
                const float* wrow = l2w + e * HDIM;
#pragma unroll 8
                for (int k0 = 0; k0 < HDIM; k0 += 4) {
                    float4 a4 = *(const float4*)(orow + k0);
                    float4 w4 = __ldg((const float4*)(wrow + k0));
                    acc += a4.x * w4.x + a4.y * w4.y + a4.z * w4.z + a4.w * w4.w;
                }
                size_t gb = bg0 + b;
                out[OFF_DECOUT + gb * (TTGT * 4) + (size_t)(td + 1) * 4 + e] = acc;
                float y = __ldg(tgt + gb * (TTGT * 4) + (size_t)(td + 1) * 4 + e);
                float d = acc - y;
                lossAcc += d * d;
            }
            // no sync needed: next write to o1 is behind next step's barriers
        }
    }

    __syncthreads();
    // dec_hidden (final h) -> out — de-swizzle
    for (int i = tid; i < NL * BC * HDIM; i += NTHR) {
        int l = i >> 11;
        int b = (i >> 7) & 15;
        int j = i & 127;
        out[OFF_DECH + (size_t)l * BATCH * HDIM + (bg0 + b) * HDIM + j] =
            SH[SM_H + l * BC * HDIM + b * HDIM + swz_j(b, j)];
    }

    // deterministic CTA loss partial (reuse o1 region as scratch; o1 dead now)
    __syncthreads();
    SH[SM_RED + tid] = lossAcc;
    __syncthreads();
    for (int o = NTHR / 2; o > 0; o >>= 1) {
        if (tid < o) SH[SM_RED + tid] += SH[SM_RED + tid + o];
        __syncthreads();
    }
    if (tid == 0) g_lossPart[cta] = SH[SM_RED];
}

__global__ void loss_reduce_kernel(float* __restrict__ out)
{
    __shared__ float s[NCTA];
    int tid = threadIdx.x;
    s[tid] = g_lossPart[tid];
    __syncthreads();
    for (int o = NCTA / 2; o > 0; o >>= 1) {
        if (tid < o) s[tid] += s[tid + o];
        __syncthreads();
    }
    if (tid == 0) out[OFF_LOSS] = s[0] * (1.0f / (float)(BATCH * 4));
}

extern "C" void kernel_launch(void* const* d_in, const int* in_sizes, int n_in,
                              void* d_out, int out_size)
{
    const float* inp    = (const float*)d_in[0];
    const float* tgt    = (const float*)d_in[1];
    const float* e_wih0 = (const float*)d_in[2];
    const float* e_whh0 = (const float*)d_in[3];
    const float* e_wih  = (const float*)d_in[4];
    const float* e_whh  = (const float*)d_in[5];
    const float* e_bih  = (const float*)d_in[6];
    const float* e_bhh  = (const float*)d_in[7];
    const float* d_wih0 = (const float*)d_in[8];
    const float* d_whh0 = (const float*)d_in[9];
    const float* d_wih  = (const float*)d_in[10];
    const float* d_whh  = (const float*)d_in[11];
    const float* d_bih  = (const float*)d_in[12];
    const float* d_bhh  = (const float*)d_in[13];
    const float* l1w    = (const float*)d_in[14];
    const float* l1b    = (const float*)d_in[15];
    const float* l2w    = (const float*)d_in[16];
    const float* l2b    = (const float*)d_in[17];
    float* out = (float*)d_out;

    gru_seq2seq_kernel<<<NCTA, NTHR, SM_FLOATS * sizeof(float)>>>(
        inp, tgt, e_wih0, e_whh0, e_wih, e_whh, e_bih, e_bhh,
        d_wih0, d_whh0, d_wih, d_whh, d_bih, d_bhh,
        l1w, l1b, l2w, l2b, out);
    loss_reduce_kernel<<<1, NCTA>>>(out);
}